// round 7
// baseline (speedup 1.0000x reference)
#include <cuda_runtime.h>
#include <cstdint>

// Problem constants (from reference)
#define PCR0      (-51.2f)
#define VX        (0.05f)
#define STRIDE_F  (4.0f)
#define FW        512
#define FH        512
#define NUM_CLASSES 10
#define NUM_MAX_OBJS 500
#define BATCH     16
#define OVERLAP   (0.1f)
#define MIN_RADIUS 2
#define RMAX      16
#define EPS_F32   (1.1920929e-07f)

#define HEAT_ELEMS   ((size_t)BATCH * NUM_CLASSES * FH * FW)
#define BOXES_ELEMS  ((size_t)BATCH * NUM_MAX_OBJS * 8)
#define INDS_ELEMS   ((size_t)BATCH * NUM_MAX_OBJS)

#define TOBJ   (BATCH * NUM_MAX_OBJS)      // 8000
#define NTX    8                            // 512/64 tiles per row
#define TILES_PER_PLANE 64
#define NTILE  (BATCH * NUM_CLASSES * TILES_PER_PLANE)  // 10240
#define CAP    64
#define TABW   17                           // RMAX+1

// Static device scratch (zero-initialized at module load; d_cnt is
// self-cleaned by gather_kernel each run -> deterministic replays).
__device__ int   d_cnt [NTILE];
__device__ int   d_list[NTILE * CAP];
__device__ float d_exp [TOBJ * TABW];
__device__ int4  d_meta[TOBJ];              // {cxi, cyi, r, pad}

__device__ __forceinline__ float gaussian_radius(float h, float w, float ov) {
    float b1 = h + w;
    float c1 = w * h * (1.0f - ov) / (1.0f + ov);
    float sq1 = sqrtf(fmaxf(b1 * b1 - 4.0f * c1, 0.0f));
    float r1 = (b1 + sq1) * 0.5f;

    float b2 = 2.0f * (h + w);
    float c2 = (1.0f - ov) * w * h;
    float sq2 = sqrtf(fmaxf(b2 * b2 - 16.0f * c2, 0.0f));
    float r2 = (b2 + sq2) * 0.5f;

    float a3 = 4.0f * ov;
    float b3 = -2.0f * ov * (h + w);
    float c3 = (ov - 1.0f) * w * h;
    float sq3 = sqrtf(fmaxf(b3 * b3 - 4.0f * a3 * c3, 0.0f));
    float r3 = (b3 + sq3) / (2.0f * a3);

    return fminf(fminf(r1, r2), r3);
}

// One thread per object: params, exp table (zero-padded to 17), meta,
// tile binning, and the per-object outputs.
__global__ void bin_kernel(const float* __restrict__ gt,
                           float* __restrict__ boxes,
                           float* __restrict__ inds,
                           float* __restrict__ mask)
{
    const int obj = blockIdx.x * blockDim.x + threadIdx.x;
    if (obj >= TOBJ) return;
    const int b = obj / NUM_MAX_OBJS;

    const float* g = gt + (size_t)obj * 8;
    const float x  = g[0], y  = g[1], z  = g[2];
    const float dx = g[3], dy = g[4], dz = g[5];
    const float hd = g[6];
    const int   cls = (int)(g[7] - 1.0f);

    float coord_x = (x - PCR0) / VX / STRIDE_F;
    float coord_y = (y - PCR0) / VX / STRIDE_F;
    coord_x = fminf(fmaxf(coord_x, 0.0f), (float)FW - 0.5f);
    coord_y = fminf(fmaxf(coord_y, 0.0f), (float)FH - 0.5f);
    const int cxi = (int)coord_x;
    const int cyi = (int)coord_y;

    const float dxf = dx / VX / STRIDE_F;
    const float dyf = dy / VX / STRIDE_F;

    int r = (int)gaussian_radius(dxf, dyf, OVERLAP);
    r = min(max(r, MIN_RADIUS), RMAX);

    const bool valid = (dxf > 0.0f) && (dyf > 0.0f) &&
                       (cxi >= 0) && (cxi <= FW) &&
                       (cyi >= 0) && (cyi <= FH);

    {
        const float vf = valid ? 1.0f : 0.0f;
        float* bo = boxes + (size_t)obj * 8;
        bo[0] = (coord_x - (float)cxi) * vf;
        bo[1] = (coord_y - (float)cyi) * vf;
        bo[2] = z * vf;
        bo[3] = logf(fmaxf(dx, 1e-12f)) * vf;
        bo[4] = logf(fmaxf(dy, 1e-12f)) * vf;
        bo[5] = logf(fmaxf(dz, 1e-12f)) * vf;
        bo[6] = cosf(hd) * vf;
        bo[7] = sinf(hd) * vf;
        inds[obj] = valid ? (float)(cyi * FW + cxi) : 0.0f;
        mask[obj] = vf;
    }

    if (!valid) return;

    const float sigma  = (2.0f * (float)r + 1.0f) / 6.0f;
    const float inv2s2 = 1.0f / (2.0f * sigma * sigma);
    float* tab = &d_exp[obj * TABW];
    #pragma unroll
    for (int k = 0; k < TABW; k++)
        tab[k] = (k <= r) ? expf(-(float)(k * k) * inv2s2) : 0.0f;

    d_meta[obj] = make_int4(cxi, cyi, r, 0);

    const int c = min(max(cls, 0), NUM_CLASSES - 1);
    const int ty0 = max(cyi - r, 0) >> 6;
    const int ty1 = min(cyi + r, FH - 1) >> 6;
    const int tx0 = max(cxi - r, 0) >> 6;
    const int tx1 = min(cxi + r, FW - 1) >> 6;
    const int pbase = (b * NUM_CLASSES + c) * TILES_PER_PLANE;
    for (int ty = ty0; ty <= ty1; ty++)
        for (int tx = tx0; tx <= tx1; tx++) {
            const int t = pbase + ty * NTX + tx;
            const int idx = atomicAdd(&d_cnt[t], 1);
            if (idx < CAP) d_list[t * CAP + idx] = obj;
        }
}

// One 1024-thread block per 64x64 tile of one (batch,class) plane.
// Thread = 4 consecutive pixels = one float4 store, lane-consecutive
// addresses (warp writes two full 256B segments). The store doubles as
// the zero-fill: every heatmap element written exactly once, no memset,
// no atomics on the heatmap.
__global__ void __launch_bounds__(1024) gather_kernel(float* __restrict__ heat)
{
    __shared__ int4  smeta[CAP];
    __shared__ float stab [CAP * TABW];

    const int blk  = blockIdx.x;
    const int tile = blk & (TILES_PER_PLANE - 1);
    const int pc   = blk >> 6;                 // b*NUM_CLASSES + c
    const int tx   = tile & (NTX - 1);
    const int ty   = tile >> 3;

    const int tid = threadIdx.x;
    const int row = tid >> 4;                  // 0..63
    const int y   = (ty << 6) + row;
    const int x0  = (tx << 6) + ((tid & 15) << 2);   // 4-px strip

    const int n = min(d_cnt[blk], CAP);

    if (n > 0) {
        for (int i = tid; i < n; i += 1024)
            smeta[i] = d_meta[d_list[blk * CAP + i]];
        const int tot = n * TABW;
        for (int j = tid; j < tot; j += 1024) {
            const int i = j / TABW;
            const int k = j - i * TABW;
            stab[j] = d_exp[d_list[blk * CAP + i] * TABW + k];
        }
        __syncthreads();
    }
    // Self-clean the counter for the next graph replay (read-before-write:
    // all threads read d_cnt above; in the n>0 path the barrier orders the
    // write after every read; in the n==0 path the write is 0-over-0).
    if (tid == 0) d_cnt[blk] = 0;

    float a0 = 0.f, a1 = 0.f, a2 = 0.f, a3 = 0.f;

    for (int i = 0; i < n; i++) {
        const int4 m  = smeta[i];              // cx, cy, r
        const int ady = abs(y - m.y);
        if (ady > m.z) continue;
        const int d0 = x0 - m.x;
        if (d0 > m.z || d0 + 3 < -m.z) continue;
        const float* t = &stab[i * TABW];
        const float fi = t[ady];
        {
            const int adx = abs(d0);
            if (adx <= RMAX) { const float v = fi * t[adx]; if (v >= EPS_F32) a0 = fmaxf(a0, v); }
        }
        {
            const int adx = abs(d0 + 1);
            if (adx <= RMAX) { const float v = fi * t[adx]; if (v >= EPS_F32) a1 = fmaxf(a1, v); }
        }
        {
            const int adx = abs(d0 + 2);
            if (adx <= RMAX) { const float v = fi * t[adx]; if (v >= EPS_F32) a2 = fmaxf(a2, v); }
        }
        {
            const int adx = abs(d0 + 3);
            if (adx <= RMAX) { const float v = fi * t[adx]; if (v >= EPS_F32) a3 = fmaxf(a3, v); }
        }
    }

    float* p = heat + ((size_t)pc * FH + y) * FW + x0;
    *(float4*)p = make_float4(a0, a1, a2, a3);
}

extern "C" void kernel_launch(void* const* d_in, const int* in_sizes, int n_in,
                              void* d_out, int out_size) {
    const float* gt = (const float*)d_in[0];
    float* out = (float*)d_out;

    float* heat  = out;
    float* boxes = out + HEAT_ELEMS;
    float* inds  = out + HEAT_ELEMS + BOXES_ELEMS;
    float* mask  = out + HEAT_ELEMS + BOXES_ELEMS + INDS_ELEMS;

    bin_kernel<<<(TOBJ + 255) / 256, 256>>>(gt, boxes, inds, mask);
    gather_kernel<<<NTILE, 1024>>>(heat);
}

// round 8
// speedup vs baseline: 1.8083x; 1.8083x over previous
#include <cuda_runtime.h>
#include <cstdint>

// Problem constants (from reference)
#define PCR0      (-51.2f)
#define VX        (0.05f)
#define STRIDE_F  (4.0f)
#define FW        512
#define FH        512
#define NUM_CLASSES 10
#define NUM_MAX_OBJS 500
#define BATCH     16
#define OVERLAP   (0.1f)
#define MIN_RADIUS 2
#define RMAX      16
#define EPS_F32   (1.1920929e-07f)

#define HEAT_ELEMS   ((size_t)BATCH * NUM_CLASSES * FH * FW)
#define BOXES_ELEMS  ((size_t)BATCH * NUM_MAX_OBJS * 8)
#define INDS_ELEMS   ((size_t)BATCH * NUM_MAX_OBJS)

#define TOBJ   (BATCH * NUM_MAX_OBJS)      // 8000
#define NTX    8                            // 512/64 tiles per row
#define TILES_PER_PLANE 64
#define NTILE  (BATCH * NUM_CLASSES * TILES_PER_PLANE)  // 10240
#define CAP    32
#define TABW   17                           // RMAX+1

// Static device scratch. d_cnt starts zeroed (static init) and is
// self-cleaned at the end of gather_kernel -> deterministic graph replays.
__device__ int   d_cnt    [NTILE];
__device__ int4  d_tilemeta[NTILE * CAP];          // {cxi, cyi, r, pad}
__device__ float d_tiletab [NTILE * CAP * TABW];   // zero-padded exp tables

__device__ __forceinline__ float gaussian_radius(float h, float w, float ov) {
    float b1 = h + w;
    float c1 = w * h * (1.0f - ov) / (1.0f + ov);
    float sq1 = sqrtf(fmaxf(b1 * b1 - 4.0f * c1, 0.0f));
    float r1 = (b1 + sq1) * 0.5f;

    float b2 = 2.0f * (h + w);
    float c2 = (1.0f - ov) * w * h;
    float sq2 = sqrtf(fmaxf(b2 * b2 - 16.0f * c2, 0.0f));
    float r2 = (b2 + sq2) * 0.5f;

    float a3 = 4.0f * ov;
    float b3 = -2.0f * ov * (h + w);
    float c3 = (ov - 1.0f) * w * h;
    float sq3 = sqrtf(fmaxf(b3 * b3 - 4.0f * a3 * c3, 0.0f));
    float r3 = (b3 + sq3) / (2.0f * a3);

    return fminf(fminf(r1, r2), r3);
}

// One thread per object: per-object outputs, then write meta + exp table
// directly into every intersecting tile's slot (no obj indirection later).
__global__ void bin_kernel(const float* __restrict__ gt,
                           float* __restrict__ boxes,
                           float* __restrict__ inds,
                           float* __restrict__ mask)
{
    const int obj = blockIdx.x * blockDim.x + threadIdx.x;
    if (obj >= TOBJ) return;
    const int b = obj / NUM_MAX_OBJS;

    const float* g = gt + (size_t)obj * 8;
    const float x  = g[0], y  = g[1], z  = g[2];
    const float dx = g[3], dy = g[4], dz = g[5];
    const float hd = g[6];
    const int   cls = (int)(g[7] - 1.0f);

    float coord_x = (x - PCR0) / VX / STRIDE_F;
    float coord_y = (y - PCR0) / VX / STRIDE_F;
    coord_x = fminf(fmaxf(coord_x, 0.0f), (float)FW - 0.5f);
    coord_y = fminf(fmaxf(coord_y, 0.0f), (float)FH - 0.5f);
    const int cxi = (int)coord_x;
    const int cyi = (int)coord_y;

    const float dxf = dx / VX / STRIDE_F;
    const float dyf = dy / VX / STRIDE_F;

    int r = (int)gaussian_radius(dxf, dyf, OVERLAP);
    r = min(max(r, MIN_RADIUS), RMAX);

    const bool valid = (dxf > 0.0f) && (dyf > 0.0f) &&
                       (cxi >= 0) && (cxi <= FW) &&
                       (cyi >= 0) && (cyi <= FH);

    {
        const float vf = valid ? 1.0f : 0.0f;
        float* bo = boxes + (size_t)obj * 8;
        bo[0] = (coord_x - (float)cxi) * vf;
        bo[1] = (coord_y - (float)cyi) * vf;
        bo[2] = z * vf;
        bo[3] = logf(fmaxf(dx, 1e-12f)) * vf;
        bo[4] = logf(fmaxf(dy, 1e-12f)) * vf;
        bo[5] = logf(fmaxf(dz, 1e-12f)) * vf;
        bo[6] = cosf(hd) * vf;
        bo[7] = sinf(hd) * vf;
        inds[obj] = valid ? (float)(cyi * FW + cxi) : 0.0f;
        mask[obj] = vf;
    }

    if (!valid) return;

    // Zero-padded 1D gaussian table in registers
    const float sigma  = (2.0f * (float)r + 1.0f) / 6.0f;
    const float inv2s2 = 1.0f / (2.0f * sigma * sigma);
    float tab[TABW];
    #pragma unroll
    for (int k = 0; k < TABW; k++)
        tab[k] = (k <= r) ? expf(-(float)(k * k) * inv2s2) : 0.0f;

    const int c = min(max(cls, 0), NUM_CLASSES - 1);
    const int ty0 = max(cyi - r, 0) >> 6;
    const int ty1 = min(cyi + r, FH - 1) >> 6;
    const int tx0 = max(cxi - r, 0) >> 6;
    const int tx1 = min(cxi + r, FW - 1) >> 6;
    const int pbase = (b * NUM_CLASSES + c) * TILES_PER_PLANE;
    for (int ty = ty0; ty <= ty1; ty++)
        for (int tx = tx0; tx <= tx1; tx++) {
            const int t = pbase + ty * NTX + tx;
            const int idx = atomicAdd(&d_cnt[t], 1);
            if (idx < CAP) {
                const int slot = t * CAP + idx;
                d_tilemeta[slot] = make_int4(cxi, cyi, r, 0);
                float* dst = &d_tiletab[slot * TABW];
                #pragma unroll
                for (int k = 0; k < TABW; k++) dst[k] = tab[k];
            }
        }
}

// One 256-thread block per 64x64 tile. No smem, no mid-kernel barrier:
// each warp independently reads the tile's slots and writes its pixels.
// Thread = 16 px of one row as 4 float4 stores at x = base + q*16
// (4-lane clusters write contiguous 64B). Stores double as zero-fill.
__global__ void __launch_bounds__(256) gather_kernel(float* __restrict__ heat)
{
    const int blk  = blockIdx.x;
    const int tile = blk & (TILES_PER_PLANE - 1);
    const int pc   = blk >> 6;                 // b*NUM_CLASSES + c
    const int tx   = tile & (NTX - 1);
    const int ty   = tile >> 3;

    const int tid  = threadIdx.x;
    const int row  = tid >> 2;                 // 0..63
    const int y    = (ty << 6) + row;
    const int xb   = (tx << 6) + ((tid & 3) << 2);  // q-th px at xb + q*16

    const int n = min(d_cnt[blk], CAP);

    float acc[4][4];
    #pragma unroll
    for (int q = 0; q < 4; q++)
        #pragma unroll
        for (int k = 0; k < 4; k++) acc[q][k] = 0.0f;

    for (int i = 0; i < n; i++) {
        const int slot = blk * CAP + i;
        const int4 m = __ldg(&d_tilemeta[slot]);      // cx, cy, r
        const int ady = abs(y - m.y);
        if (ady > m.z) continue;
        const float* t = &d_tiletab[slot * TABW];
        const float fi = __ldg(&t[ady]);
        #pragma unroll
        for (int q = 0; q < 4; q++) {
            const int d = xb + q * 16 - m.x;          // offset of k=0 px
            if (d > RMAX || d + 3 < -RMAX) continue;  // 4-px strip reject
            #pragma unroll
            for (int k = 0; k < 4; k++) {
                const int adx = abs(d + k);
                if (adx <= RMAX) {
                    const float v = fi * __ldg(&t[adx]);
                    if (v >= EPS_F32)
                        acc[q][k] = fmaxf(acc[q][k], v);
                }
            }
        }
    }

    float* prow = heat + ((size_t)pc * FH + y) * FW;
    #pragma unroll
    for (int q = 0; q < 4; q++)
        *(float4*)(prow + xb + q * 16) =
            make_float4(acc[q][0], acc[q][1], acc[q][2], acc[q][3]);

    // Self-clean the counter for the next replay. Barrier is at the END:
    // it orders the reset after every warp's d_cnt read without adding any
    // latency to the store path.
    __syncthreads();
    if (tid == 0) d_cnt[blk] = 0;
}

extern "C" void kernel_launch(void* const* d_in, const int* in_sizes, int n_in,
                              void* d_out, int out_size) {
    const float* gt = (const float*)d_in[0];
    float* out = (float*)d_out;

    float* heat  = out;
    float* boxes = out + HEAT_ELEMS;
    float* inds  = out + HEAT_ELEMS + BOXES_ELEMS;
    float* mask  = out + HEAT_ELEMS + BOXES_ELEMS + INDS_ELEMS;

    bin_kernel<<<(TOBJ + 255) / 256, 256>>>(gt, boxes, inds, mask);
    gather_kernel<<<NTILE, 256>>>(heat);
}

// round 9
// speedup vs baseline: 2.1896x; 1.2109x over previous
#include <cuda_runtime.h>
#include <cstdint>

// Problem constants (from reference)
#define PCR0      (-51.2f)
#define VX        (0.05f)
#define STRIDE_F  (4.0f)
#define FW        512
#define FH        512
#define NUM_CLASSES 10
#define NUM_MAX_OBJS 500
#define BATCH     16
#define OVERLAP   (0.1f)
#define MIN_RADIUS 2
#define RMAX      16
#define EPS_F32   (1.1920929e-07f)

#define HEAT_ELEMS   ((size_t)BATCH * NUM_CLASSES * FH * FW)
#define BOXES_ELEMS  ((size_t)BATCH * NUM_MAX_OBJS * 8)
#define INDS_ELEMS   ((size_t)BATCH * NUM_MAX_OBJS)

#define TOBJ   (BATCH * NUM_MAX_OBJS)      // 8000
#define NTX    8                            // 512/64 tiles per row
#define TILES_PER_PLANE 64
#define NTILE  (BATCH * NUM_CLASSES * TILES_PER_PLANE)  // 10240
#define CAP    32

// Static device scratch. d_cnt starts zeroed (static init) and is
// self-cleaned at the end of gather_kernel -> deterministic graph replays.
__device__ int  d_cnt     [NTILE];
__device__ int4 d_tilemeta[NTILE * CAP];   // {cxi, cyi, r, bits(-1/(2 sigma^2))}

__device__ __forceinline__ float gaussian_radius(float h, float w, float ov) {
    float b1 = h + w;
    float c1 = w * h * (1.0f - ov) / (1.0f + ov);
    float sq1 = sqrtf(fmaxf(b1 * b1 - 4.0f * c1, 0.0f));
    float r1 = (b1 + sq1) * 0.5f;

    float b2 = 2.0f * (h + w);
    float c2 = (1.0f - ov) * w * h;
    float sq2 = sqrtf(fmaxf(b2 * b2 - 16.0f * c2, 0.0f));
    float r2 = (b2 + sq2) * 0.5f;

    float a3 = 4.0f * ov;
    float b3 = -2.0f * ov * (h + w);
    float c3 = (ov - 1.0f) * w * h;
    float sq3 = sqrtf(fmaxf(b3 * b3 - 4.0f * a3 * c3, 0.0f));
    float r3 = (b3 + sq3) / (2.0f * a3);

    return fminf(fminf(r1, r2), r3);
}

// One thread per object: per-object outputs + one int4 per intersecting tile.
__global__ void bin_kernel(const float* __restrict__ gt,
                           float* __restrict__ boxes,
                           float* __restrict__ inds,
                           float* __restrict__ mask)
{
    const int obj = blockIdx.x * blockDim.x + threadIdx.x;
    if (obj >= TOBJ) return;
    const int b = obj / NUM_MAX_OBJS;

    const float* g = gt + (size_t)obj * 8;
    const float x  = g[0], y  = g[1], z  = g[2];
    const float dx = g[3], dy = g[4], dz = g[5];
    const float hd = g[6];
    const int   cls = (int)(g[7] - 1.0f);

    float coord_x = (x - PCR0) / VX / STRIDE_F;
    float coord_y = (y - PCR0) / VX / STRIDE_F;
    coord_x = fminf(fmaxf(coord_x, 0.0f), (float)FW - 0.5f);
    coord_y = fminf(fmaxf(coord_y, 0.0f), (float)FH - 0.5f);
    const int cxi = (int)coord_x;
    const int cyi = (int)coord_y;

    const float dxf = dx / VX / STRIDE_F;
    const float dyf = dy / VX / STRIDE_F;

    int r = (int)gaussian_radius(dxf, dyf, OVERLAP);
    r = min(max(r, MIN_RADIUS), RMAX);

    const bool valid = (dxf > 0.0f) && (dyf > 0.0f) &&
                       (cxi >= 0) && (cxi <= FW) &&
                       (cyi >= 0) && (cyi <= FH);

    {
        const float vf = valid ? 1.0f : 0.0f;
        float* bo = boxes + (size_t)obj * 8;
        bo[0] = (coord_x - (float)cxi) * vf;
        bo[1] = (coord_y - (float)cyi) * vf;
        bo[2] = z * vf;
        bo[3] = logf(fmaxf(dx, 1e-12f)) * vf;
        bo[4] = logf(fmaxf(dy, 1e-12f)) * vf;
        bo[5] = logf(fmaxf(dz, 1e-12f)) * vf;
        bo[6] = cosf(hd) * vf;
        bo[7] = sinf(hd) * vf;
        inds[obj] = valid ? (float)(cyi * FW + cxi) : 0.0f;
        mask[obj] = vf;
    }

    if (!valid) return;

    const float sigma  = (2.0f * (float)r + 1.0f) / 6.0f;
    const float ninv2s2 = -1.0f / (2.0f * sigma * sigma);
    const int4 meta = make_int4(cxi, cyi, r, __float_as_int(ninv2s2));

    const int c = min(max(cls, 0), NUM_CLASSES - 1);
    const int ty0 = max(cyi - r, 0) >> 6;
    const int ty1 = min(cyi + r, FH - 1) >> 6;
    const int tx0 = max(cxi - r, 0) >> 6;
    const int tx1 = min(cxi + r, FW - 1) >> 6;
    const int pbase = (b * NUM_CLASSES + c) * TILES_PER_PLANE;
    for (int ty = ty0; ty <= ty1; ty++)
        for (int tx = tx0; tx <= tx1; tx++) {
            const int t = pbase + ty * NTX + tx;
            const int idx = atomicAdd(&d_cnt[t], 1);
            if (idx < CAP) d_tilemeta[t * CAP + idx] = meta;
        }
}

// One 256-thread block per 64x64 tile of one (batch,class) plane.
// Thread = fixed 4-px column strip (x = (tid&15)*4), 4 rows (q*16 + tid>>4).
// Lanes 0-15 of a warp cover 256B contiguous; each warp STG.128 writes
// fully-covered 128B lines. Stores double as the zero-fill: every heatmap
// element written exactly once; no memset, no atomics, no smem, no tables.
__global__ void __launch_bounds__(256) gather_kernel(float* __restrict__ heat)
{
    const int blk  = blockIdx.x;
    const int tile = blk & (TILES_PER_PLANE - 1);
    const int pc   = blk >> 6;                 // b*NUM_CLASSES + c
    const int tx   = tile & (NTX - 1);
    const int ty   = tile >> 3;

    const int tid  = threadIdx.x;
    const int x0   = (tx << 6) + ((tid & 15) << 2);   // fixed 4-px strip
    const int r0   = (ty << 6) + (tid >> 4);          // rows r0 + q*16

    const int n = min(d_cnt[blk], CAP);

    float acc[4][4];
    #pragma unroll
    for (int q = 0; q < 4; q++)
        #pragma unroll
        for (int k = 0; k < 4; k++) acc[q][k] = 0.0f;

    for (int i = 0; i < n; i++) {
        const int4 m = __ldg(&d_tilemeta[blk * CAP + i]);  // cx, cy, r, a
        const int d0 = x0 - m.x;
        if (d0 > m.z || d0 + 3 < -m.z) continue;           // column strip reject
        const float a = __int_as_float(m.w);               // -1/(2 sigma^2)

        // Column factors: fixed x -> computed once per object
        float fj[4];
        #pragma unroll
        for (int k = 0; k < 4; k++) {
            const int adx = abs(d0 + k);
            const float fd = (float)(adx * adx);
            fj[k] = (adx <= m.z) ? __expf(fd * a) : 0.0f;
        }

        #pragma unroll
        for (int q = 0; q < 4; q++) {
            const int ady = abs(r0 + q * 16 - m.y);
            if (ady > m.z) continue;
            const float fi = __expf((float)(ady * ady) * a);
            #pragma unroll
            for (int k = 0; k < 4; k++) {
                const float v = fi * fj[k];
                if (v >= EPS_F32)
                    acc[q][k] = fmaxf(acc[q][k], v);
            }
        }
    }

    float* base = heat + ((size_t)pc * FH) * FW;
    #pragma unroll
    for (int q = 0; q < 4; q++)
        *(float4*)(base + (size_t)(r0 + q * 16) * FW + x0) =
            make_float4(acc[q][0], acc[q][1], acc[q][2], acc[q][3]);

    // Self-clean the counter for the next replay; barrier at the END orders
    // the reset after every thread's d_cnt read without slowing the prologue.
    __syncthreads();
    if (tid == 0) d_cnt[blk] = 0;
}

extern "C" void kernel_launch(void* const* d_in, const int* in_sizes, int n_in,
                              void* d_out, int out_size) {
    const float* gt = (const float*)d_in[0];
    float* out = (float*)d_out;

    float* heat  = out;
    float* boxes = out + HEAT_ELEMS;
    float* inds  = out + HEAT_ELEMS + BOXES_ELEMS;
    float* mask  = out + HEAT_ELEMS + BOXES_ELEMS + INDS_ELEMS;

    bin_kernel<<<(TOBJ + 127) / 128, 128>>>(gt, boxes, inds, mask);
    gather_kernel<<<NTILE, 256>>>(heat);
}

// round 10
// speedup vs baseline: 2.3156x; 1.0576x over previous
#include <cuda_runtime.h>
#include <cstdint>

// Problem constants (from reference)
#define PCR0      (-51.2f)
#define VX        (0.05f)
#define STRIDE_F  (4.0f)
#define FW        512
#define FH        512
#define NUM_CLASSES 10
#define NUM_MAX_OBJS 500
#define BATCH     16
#define OVERLAP   (0.1f)
#define MIN_RADIUS 2
#define RMAX      16

#define HEAT_ELEMS   ((size_t)BATCH * NUM_CLASSES * FH * FW)
#define BOXES_ELEMS  ((size_t)BATCH * NUM_MAX_OBJS * 8)
#define INDS_ELEMS   ((size_t)BATCH * NUM_MAX_OBJS)

#define TOBJ   (BATCH * NUM_MAX_OBJS)      // 8000
#define NTX    8                            // 512/64 tiles per row
#define TILES_PER_PLANE 64
#define NTILE  (BATCH * NUM_CLASSES * TILES_PER_PLANE)  // 10240
#define CAP    32

// Static device scratch. d_cnt starts zeroed (static init) and is
// self-cleaned at the end of gather_kernel -> deterministic graph replays.
__device__ int  d_cnt     [NTILE];
__device__ int4 d_tilemeta[NTILE * CAP];   // {cxi, cyi, r, bits(-1/(2 sigma^2))}

__device__ __forceinline__ float gaussian_radius(float h, float w, float ov) {
    float b1 = h + w;
    float c1 = w * h * (1.0f - ov) / (1.0f + ov);
    float sq1 = sqrtf(fmaxf(b1 * b1 - 4.0f * c1, 0.0f));
    float r1 = (b1 + sq1) * 0.5f;

    float b2 = 2.0f * (h + w);
    float c2 = (1.0f - ov) * w * h;
    float sq2 = sqrtf(fmaxf(b2 * b2 - 16.0f * c2, 0.0f));
    float r2 = (b2 + sq2) * 0.5f;

    float a3 = 4.0f * ov;
    float b3 = -2.0f * ov * (h + w);
    float c3 = (ov - 1.0f) * w * h;
    float sq3 = sqrtf(fmaxf(b3 * b3 - 4.0f * a3 * c3, 0.0f));
    float r3 = (b3 + sq3) / (2.0f * a3);

    return fminf(fminf(r1, r2), r3);
}

// One thread per object: per-object outputs + one int4 per intersecting tile.
// IEEE div/sqrt kept for everything feeding int casts (cxi/cyi/r);
// fast intrinsics only for continuous outputs (log/cos/sin).
__global__ void __launch_bounds__(64) bin_kernel(
        const float* __restrict__ gt,
        float* __restrict__ boxes,
        float* __restrict__ inds,
        float* __restrict__ mask)
{
    const int obj = blockIdx.x * blockDim.x + threadIdx.x;
    if (obj >= TOBJ) return;
    const int b = obj / NUM_MAX_OBJS;

    // Two 16B loads instead of 8 scalar LDGs
    const float4 g0 = __ldg((const float4*)(gt + (size_t)obj * 8));
    const float4 g1 = __ldg((const float4*)(gt + (size_t)obj * 8) + 1);
    const float x  = g0.x, y  = g0.y, z = g0.z, dx = g0.w;
    const float dy = g1.x, dz = g1.y, hd = g1.z;
    const int   cls = (int)(g1.w - 1.0f);

    float coord_x = (x - PCR0) / VX / STRIDE_F;
    float coord_y = (y - PCR0) / VX / STRIDE_F;
    coord_x = fminf(fmaxf(coord_x, 0.0f), (float)FW - 0.5f);
    coord_y = fminf(fmaxf(coord_y, 0.0f), (float)FH - 0.5f);
    const int cxi = (int)coord_x;
    const int cyi = (int)coord_y;

    const float dxf = dx / VX / STRIDE_F;
    const float dyf = dy / VX / STRIDE_F;

    int r = (int)gaussian_radius(dxf, dyf, OVERLAP);
    r = min(max(r, MIN_RADIUS), RMAX);

    const bool valid = (dxf > 0.0f) && (dyf > 0.0f) &&
                       (cxi >= 0) && (cxi <= FW) &&
                       (cyi >= 0) && (cyi <= FH);

    {
        const float vf = valid ? 1.0f : 0.0f;
        float* bo = boxes + (size_t)obj * 8;
        bo[0] = (coord_x - (float)cxi) * vf;
        bo[1] = (coord_y - (float)cyi) * vf;
        bo[2] = z * vf;
        bo[3] = __logf(fmaxf(dx, 1e-12f)) * vf;
        bo[4] = __logf(fmaxf(dy, 1e-12f)) * vf;
        bo[5] = __logf(fmaxf(dz, 1e-12f)) * vf;
        bo[6] = __cosf(hd) * vf;
        bo[7] = __sinf(hd) * vf;
        inds[obj] = valid ? (float)(cyi * FW + cxi) : 0.0f;
        mask[obj] = vf;
    }

    if (!valid) return;

    const float sigma   = (2.0f * (float)r + 1.0f) / 6.0f;
    const float ninv2s2 = -1.0f / (2.0f * sigma * sigma);
    const int4 meta = make_int4(cxi, cyi, r, __float_as_int(ninv2s2));

    const int c = min(max(cls, 0), NUM_CLASSES - 1);
    const int ty0 = max(cyi - r, 0) >> 6;
    const int ty1 = min(cyi + r, FH - 1) >> 6;
    const int tx0 = max(cxi - r, 0) >> 6;
    const int tx1 = min(cxi + r, FW - 1) >> 6;
    const int pbase = (b * NUM_CLASSES + c) * TILES_PER_PLANE;
    for (int ty = ty0; ty <= ty1; ty++)
        for (int tx = tx0; tx <= tx1; tx++) {
            const int t = pbase + ty * NTX + tx;
            const int idx = atomicAdd(&d_cnt[t], 1);
            if (idx < CAP) d_tilemeta[t * CAP + idx] = meta;
        }
}

// One 256-thread block per 64x64 tile of one (batch,class) plane.
// Thread = fixed 4-px column strip (x = (tid&15)*4), 4 rows (q*16 + tid>>4).
// Lanes 0-15 cover 256B contiguous; warp STG.128s write fully-covered lines.
// Stores double as the zero-fill: every heatmap element written exactly once.
// No EPS guard needed: in-radius values are >= exp(-18r^2/(2r+1)^2) >= 0.014
// >> FLT_EPSILON for all r in [2,16]; out-of-radius factors are exactly 0,
// a no-op under fmaxf against the 0-initialized accumulator.
__global__ void __launch_bounds__(256) gather_kernel(float* __restrict__ heat)
{
    const int blk  = blockIdx.x;
    const int tile = blk & (TILES_PER_PLANE - 1);
    const int pc   = blk >> 6;                 // b*NUM_CLASSES + c
    const int tx   = tile & (NTX - 1);
    const int ty   = tile >> 3;

    const int tid  = threadIdx.x;
    const int x0   = (tx << 6) + ((tid & 15) << 2);   // fixed 4-px strip
    const int r0   = (ty << 6) + (tid >> 4);          // rows r0 + q*16

    const int n = min(d_cnt[blk], CAP);

    float acc[4][4];
    #pragma unroll
    for (int q = 0; q < 4; q++)
        #pragma unroll
        for (int k = 0; k < 4; k++) acc[q][k] = 0.0f;

    for (int i = 0; i < n; i++) {
        const int4 m = __ldg(&d_tilemeta[blk * CAP + i]);  // cx, cy, r, a
        const int d0 = x0 - m.x;
        if (d0 > m.z || d0 + 3 < -m.z) continue;           // column strip reject
        const float a = __int_as_float(m.w);               // -1/(2 sigma^2)

        // Column factors: fixed x -> computed once per object
        float fj[4];
        #pragma unroll
        for (int k = 0; k < 4; k++) {
            const int adx = abs(d0 + k);
            const float e = __expf((float)(adx * adx) * a);
            fj[k] = (adx <= m.z) ? e : 0.0f;
        }

        #pragma unroll
        for (int q = 0; q < 4; q++) {
            const int ady = abs(r0 + q * 16 - m.y);
            if (ady > m.z) continue;
            const float fi = __expf((float)(ady * ady) * a);
            #pragma unroll
            for (int k = 0; k < 4; k++)
                acc[q][k] = fmaxf(acc[q][k], fi * fj[k]);
        }
    }

    float* base = heat + ((size_t)pc * FH) * FW;
    #pragma unroll
    for (int q = 0; q < 4; q++)
        *(float4*)(base + (size_t)(r0 + q * 16) * FW + x0) =
            make_float4(acc[q][0], acc[q][1], acc[q][2], acc[q][3]);

    // Self-clean the counter for the next replay; barrier at the END orders
    // the reset after every thread's d_cnt read without slowing the prologue.
    __syncthreads();
    if (tid == 0) d_cnt[blk] = 0;
}

extern "C" void kernel_launch(void* const* d_in, const int* in_sizes, int n_in,
                              void* d_out, int out_size) {
    const float* gt = (const float*)d_in[0];
    float* out = (float*)d_out;

    float* heat  = out;
    float* boxes = out + HEAT_ELEMS;
    float* inds  = out + HEAT_ELEMS + BOXES_ELEMS;
    float* mask  = out + HEAT_ELEMS + BOXES_ELEMS + INDS_ELEMS;

    bin_kernel<<<(TOBJ + 63) / 64, 64>>>(gt, boxes, inds, mask);
    gather_kernel<<<NTILE, 256>>>(heat);
}